// round 1
// baseline (speedup 1.0000x reference)
#include <cuda_runtime.h>

// NTM memory module, fused single-pass kernel.
// B=2048 batch, N=512 memory slots, U=64 unit size.
// One CTA per batch element; memory[b] (128 KB) staged in dynamic SMEM.
// DRAM traffic ~= 256MB read + 256MB write -> HBM-bound, target ~80us.

#define BB 2048
#define NN 512
#define UU 64
#define THREADS 512
#define NWARPS (THREADS / 32)

// smem layout (floats):
//   s_mem : NN*UU      = 32768
//   s_wg  : NN         =   512   (logits, then wg)
//   s_w   : NN         =   512   (final weights)
//   s_red : 32         =    32   (block-reduce scratch)
//   s_k   : UU         =    64   (k[b] + 1e-16)
//   s_r   : 8*UU       =   512   (partial read-vector sums)
#define SMEM_FLOATS (NN*UU + NN + NN + 32 + UU + 8*UU)
#define SMEM_BYTES  (SMEM_FLOATS * 4)

__device__ __forceinline__ float warpSum(float v) {
    #pragma unroll
    for (int o = 16; o > 0; o >>= 1) v += __shfl_down_sync(0xffffffffu, v, o);
    return v;
}
__device__ __forceinline__ float warpMax(float v) {
    #pragma unroll
    for (int o = 16; o > 0; o >>= 1) v = fmaxf(v, __shfl_down_sync(0xffffffffu, v, o));
    return v;
}

__device__ __forceinline__ float blockSum(float v, float* s_red, int lane, int wid) {
    __syncthreads();               // protect s_red from previous use
    v = warpSum(v);
    if (lane == 0) s_red[wid] = v;
    __syncthreads();
    if (wid == 0) {
        float x = (lane < NWARPS) ? s_red[lane] : 0.0f;
        x = warpSum(x);
        if (lane == 0) s_red[0] = x;
    }
    __syncthreads();
    return s_red[0];
}

__device__ __forceinline__ float blockMax(float v, float* s_red, int lane, int wid) {
    __syncthreads();
    v = warpMax(v);
    if (lane == 0) s_red[wid] = v;
    __syncthreads();
    if (wid == 0) {
        float x = (lane < NWARPS) ? s_red[lane] : -3.4e38f;
        x = warpMax(x);
        if (lane == 0) s_red[0] = x;
    }
    __syncthreads();
    return s_red[0];
}

__global__ void __launch_bounds__(THREADS, 1) ntm_fused_kernel(
    const float* __restrict__ memory,   // (B,N,U)
    const float* __restrict__ kvec,     // (B,U)
    const float* __restrict__ beta_p,   // (1,)
    const float* __restrict__ g_p,      // (1,)
    const float* __restrict__ s_p,      // (B,3)
    const float* __restrict__ gamma_p,  // (1,)
    const float* __restrict__ w_pre,    // (B,N)
    const float* __restrict__ e_p,      // (B,U)
    const float* __restrict__ a_p,      // (B,U)
    float* __restrict__ out_w,          // (B,N)
    float* __restrict__ out_r,          // (B,U)
    float* __restrict__ out_mem)        // (B,N,U)
{
    extern __shared__ float smem[];
    float* s_mem = smem;                 // NN*UU
    float* s_wg  = s_mem + NN * UU;      // NN
    float* s_w   = s_wg + NN;            // NN
    float* s_red = s_w + NN;             // 32
    float* s_k   = s_red + 32;           // UU
    float* s_r   = s_k + UU;             // 8*UU

    const int b    = blockIdx.x;
    const int tid  = threadIdx.x;
    const int lane = tid & 31;
    const int wid  = tid >> 5;

    const float beta  = beta_p[0];
    const float g     = g_p[0];
    const float gamma = gamma_p[0];
    const float s0 = s_p[b * 3 + 0];
    const float s1 = s_p[b * 3 + 1];
    const float s2 = s_p[b * 3 + 2];

    // ---- stage memory[b] into smem (vectorized, coalesced) ----
    const float4* gmem4 = reinterpret_cast<const float4*>(memory + (size_t)b * NN * UU);
    float4* smem4 = reinterpret_cast<float4*>(s_mem);
    #pragma unroll 4
    for (int i = tid; i < NN * UU / 4; i += THREADS) smem4[i] = gmem4[i];
    if (tid < UU) s_k[tid] = kvec[b * UU + tid] + 1e-16f;
    __syncthreads();

    // ---- ||k + 1e-16|| (redundant per thread; trivial on resident smem) ----
    float ny2 = 0.0f;
    #pragma unroll
    for (int u = 0; u < UU; u++) { float kv = s_k[u]; ny2 += kv * kv; }
    const float ny = fmaxf(sqrtf(ny2), 1e-8f);

    // ---- cosine similarity -> logits = beta * sim (one warp per 32 rows) ----
    for (int n = wid; n < NN; n += NWARPS) {
        float m0 = s_mem[n * UU + lane]      + 1e-16f;
        float m1 = s_mem[n * UU + lane + 32] + 1e-16f;
        float dot = m0 * s_k[lane] + m1 * s_k[lane + 32];
        float nrm = m0 * m0 + m1 * m1;
        dot = warpSum(dot);
        nrm = warpSum(nrm);
        if (lane == 0) {
            float nx  = fmaxf(sqrtf(nrm), 1e-8f);
            s_wg[n] = beta * (dot / (nx * ny));
        }
    }
    // (blockMax below performs the needed __syncthreads)

    // ---- softmax + gate (one thread per slot: N == THREADS) ----
    float logit = 0.0f;
    {
        // s_wg written by other warps: blockMax's leading sync orders it.
        float lmax_in;
        __syncthreads();
        logit = s_wg[tid];
        lmax_in = logit;
        float mx = blockMax(lmax_in, s_red, lane, wid);
        float p  = __expf(logit - mx);
        float ps = blockSum(p, s_red, lane, wid);
        float wc = p / ps;
        float wg = wc * g + (1.0f - g) * w_pre[(size_t)b * NN + tid];
        __syncthreads();          // everyone done reading old s_wg (logits)
        s_wg[tid] = wg;
    }
    __syncthreads();

    // ---- circular shift + sharpen + renormalize ----
    float w;
    {
        int nm1 = (tid == 0)      ? NN - 1 : tid - 1;
        int np1 = (tid == NN - 1) ? 0      : tid + 1;
        float ws = s0 * s_wg[nm1] + s1 * s_wg[tid] + s2 * s_wg[np1];
        float wp = powf(ws, gamma);
        float tot = blockSum(wp, s_red, lane, wid);
        w = wp / tot + 1e-16f;
        s_w[tid] = w;
        out_w[(size_t)b * NN + tid] = w;
    }
    __syncthreads();

    // ---- read vector r[b][u] = sum_n w[n] * mem[n][u] ----
    {
        int u     = tid & (UU - 1);
        int chunk = tid >> 6;                 // 0..7, 64 rows each
        float acc = 0.0f;
        int n0 = chunk * 64;
        #pragma unroll 8
        for (int n = n0; n < n0 + 64; n++) acc += s_w[n] * s_mem[n * UU + u];
        s_r[chunk * UU + u] = acc;
    }
    __syncthreads();
    if (tid < UU) {
        float acc = 0.0f;
        #pragma unroll
        for (int c = 0; c < 8; c++) acc += s_r[c * UU + tid];
        out_r[(size_t)b * UU + tid] = acc;
    }

    // ---- write: M' = M * (1 - w e^T) + w a^T (vectorized, coalesced) ----
    {
        int col4 = tid & 15;                  // 16 float4 per row
        int row0 = tid >> 4;                  // 32 rows per sweep
        float4 e4 = reinterpret_cast<const float4*>(e_p + (size_t)b * UU)[col4];
        float4 a4 = reinterpret_cast<const float4*>(a_p + (size_t)b * UU)[col4];
        float4* omem4 = reinterpret_cast<float4*>(out_mem + (size_t)b * NN * UU);
        #pragma unroll
        for (int row = row0; row < NN; row += THREADS / 16) {
            float wn = s_w[row];
            float4 m4 = smem4[row * 16 + col4];
            float4 o4;
            o4.x = m4.x * (1.0f - wn * e4.x) + wn * a4.x;
            o4.y = m4.y * (1.0f - wn * e4.y) + wn * a4.y;
            o4.z = m4.z * (1.0f - wn * e4.z) + wn * a4.z;
            o4.w = m4.w * (1.0f - wn * e4.w) + wn * a4.w;
            omem4[row * 16 + col4] = o4;
        }
    }
}

extern "C" void kernel_launch(void* const* d_in, const int* in_sizes, int n_in,
                              void* d_out, int out_size) {
    const float* memory  = (const float*)d_in[0];
    const float* kvec    = (const float*)d_in[1];
    const float* beta_p  = (const float*)d_in[2];
    const float* g_p     = (const float*)d_in[3];
    const float* s_p     = (const float*)d_in[4];
    const float* gamma_p = (const float*)d_in[5];
    const float* w_pre   = (const float*)d_in[6];
    const float* e_p     = (const float*)d_in[7];
    const float* a_p     = (const float*)d_in[8];

    float* out_w   = (float*)d_out;                       // B*N
    float* out_r   = out_w + (size_t)BB * NN;             // B*U
    float* out_mem = out_r + (size_t)BB * UU;             // B*N*U

    static bool attr_set = false;  // idempotent host-side attribute, not a guard on work
    if (!attr_set) {
        cudaFuncSetAttribute(ntm_fused_kernel,
                             cudaFuncAttributeMaxDynamicSharedMemorySize, SMEM_BYTES);
        attr_set = true;
    }

    ntm_fused_kernel<<<BB, THREADS, SMEM_BYTES>>>(
        memory, kvec, beta_p, g_p, s_p, gamma_p, w_pre, e_p, a_p,
        out_w, out_r, out_mem);
}

// round 2
// speedup vs baseline: 1.5136x; 1.5136x over previous
#include <cuda_runtime.h>

// NTM memory module. B=2048, N=512, U=64.
// R2 design: no smem staging of memory[b] (that capped occupancy at 1 CTA/SM and
// left DRAM at 26%). memory is read from global in phase 1 (cosine) and re-read
// in phase 3 (read+write, fused) — phase-3 reads should hit L2 (resident CTA
// footprint ~95MB < 126MB L2). smem ~8.6KB -> ~6 CTAs/SM for cross-CTA overlap.

#define BB 2048
#define NN 512
#define UU 64
#define THREADS 256
#define NWARPS (THREADS / 32)
#define ROWS_PER_THREAD (NN / THREADS)   // 2

__device__ __forceinline__ float warpSum(float v) {
    #pragma unroll
    for (int o = 16; o > 0; o >>= 1) v += __shfl_down_sync(0xffffffffu, v, o);
    return v;
}
__device__ __forceinline__ float warpMax(float v) {
    #pragma unroll
    for (int o = 16; o > 0; o >>= 1) v = fmaxf(v, __shfl_down_sync(0xffffffffu, v, o));
    return v;
}
__device__ __forceinline__ float blockSum(float v, float* s_red, int lane, int wid) {
    __syncthreads();
    v = warpSum(v);
    if (lane == 0) s_red[wid] = v;
    __syncthreads();
    if (wid == 0) {
        float x = (lane < NWARPS) ? s_red[lane] : 0.0f;
        x = warpSum(x);
        if (lane == 0) s_red[0] = x;
    }
    __syncthreads();
    return s_red[0];
}
__device__ __forceinline__ float blockMax(float v, float* s_red, int lane, int wid) {
    __syncthreads();
    v = warpMax(v);
    if (lane == 0) s_red[wid] = v;
    __syncthreads();
    if (wid == 0) {
        float x = (lane < NWARPS) ? s_red[lane] : -3.4e38f;
        x = warpMax(x);
        if (lane == 0) s_red[0] = x;
    }
    __syncthreads();
    return s_red[0];
}

__global__ void __launch_bounds__(THREADS, 6) ntm_fused_kernel(
    const float* __restrict__ memory,   // (B,N,U)
    const float* __restrict__ kvec,     // (B,U)
    const float* __restrict__ beta_p,   // (1,)
    const float* __restrict__ g_p,      // (1,)
    const float* __restrict__ s_p,      // (B,3)
    const float* __restrict__ gamma_p,  // (1,)
    const float* __restrict__ w_pre,    // (B,N)
    const float* __restrict__ e_p,      // (B,U)
    const float* __restrict__ a_p,      // (B,U)
    float* __restrict__ out_w,          // (B,N)
    float* __restrict__ out_r,          // (B,U)
    float* __restrict__ out_mem)        // (B,N,U)
{
    __shared__ float s_k[UU];            // k[b] + 1e-16
    __shared__ float s_wg[NN];           // logits, then gated weights
    __shared__ float s_w[NN];            // final weights
    __shared__ float s_red[32];          // block-reduce scratch
    __shared__ float4 s_part[THREADS];   // phase-3 partial r sums (16 rowgroups x 16 col4)

    const int b    = blockIdx.x;
    const int tid  = threadIdx.x;
    const int lane = tid & 31;
    const int wid  = tid >> 5;

    const float beta  = beta_p[0];
    const float g     = g_p[0];
    const float gamma = gamma_p[0];
    const float s0 = s_p[b * 3 + 0];
    const float s1 = s_p[b * 3 + 1];
    const float s2 = s_p[b * 3 + 2];

    const float4* mem4 = reinterpret_cast<const float4*>(memory + (size_t)b * NN * UU);
    float4*       out4 = reinterpret_cast<float4*>(out_mem + (size_t)b * NN * UU);

    if (tid < UU) s_k[tid] = kvec[b * UU + tid] + 1e-16f;
    __syncthreads();

    // ||k + eps||, computed redundantly per thread from smem (cheap)
    float ny2 = 0.0f;
    {
        const float4* k4 = reinterpret_cast<const float4*>(s_k);
        #pragma unroll
        for (int i = 0; i < UU / 4; i++) {
            float4 kk = k4[i];
            ny2 += kk.x * kk.x + kk.y * kk.y + kk.z * kk.z + kk.w * kk.w;
        }
    }
    const float ny = fmaxf(sqrtf(ny2), 1e-8f);

    // ---- phase 1: cosine similarity logits, thread-per-row ----
    {
        const float4* k4 = reinterpret_cast<const float4*>(s_k);
        #pragma unroll
        for (int rr = 0; rr < ROWS_PER_THREAD; rr++) {
            int n = tid + rr * THREADS;
            const float4* row = mem4 + n * (UU / 4);
            float dot = 0.0f, nrm = 0.0f;
            #pragma unroll 4
            for (int i = 0; i < UU / 4; i++) {
                float4 m = __ldg(row + i);
                float4 kk = k4[i];
                m.x += 1e-16f; m.y += 1e-16f; m.z += 1e-16f; m.w += 1e-16f;
                dot += m.x * kk.x + m.y * kk.y + m.z * kk.z + m.w * kk.w;
                nrm += m.x * m.x + m.y * m.y + m.z * m.z + m.w * m.w;
            }
            float nx = fmaxf(sqrtf(nrm), 1e-8f);
            s_wg[n] = beta * (dot / (nx * ny));
        }
    }

    // ---- phase 2: softmax + gate + shift + sharpen + renorm ----
    {
        float logit0, logit1;
        __syncthreads();
        logit0 = s_wg[tid];
        logit1 = s_wg[tid + THREADS];
        float mx = blockMax(fmaxf(logit0, logit1), s_red, lane, wid);
        float p0 = __expf(logit0 - mx);
        float p1 = __expf(logit1 - mx);
        float ps = blockSum(p0 + p1, s_red, lane, wid);
        float wp0 = w_pre[(size_t)b * NN + tid];
        float wp1 = w_pre[(size_t)b * NN + tid + THREADS];
        // overwrite own slots only (each thread read only its own logits)
        s_wg[tid]           = (p0 / ps) * g + (1.0f - g) * wp0;
        s_wg[tid + THREADS] = (p1 / ps) * g + (1.0f - g) * wp1;
    }
    __syncthreads();

    {
        float wpw0, wpw1;
        {
            int n = tid;
            int nm1 = (n == 0) ? NN - 1 : n - 1;
            int np1 = n + 1;   // n < 256 so never wraps
            float ws = s0 * s_wg[nm1] + s1 * s_wg[n] + s2 * s_wg[np1];
            wpw0 = powf(ws, gamma);
        }
        {
            int n = tid + THREADS;
            int nm1 = n - 1;
            int np1 = (n == NN - 1) ? 0 : n + 1;
            float ws = s0 * s_wg[nm1] + s1 * s_wg[n] + s2 * s_wg[np1];
            wpw1 = powf(ws, gamma);
        }
        float tot = blockSum(wpw0 + wpw1, s_red, lane, wid);
        float w0 = wpw0 / tot + 1e-16f;
        float w1 = wpw1 / tot + 1e-16f;
        s_w[tid]           = w0;
        s_w[tid + THREADS] = w1;
        out_w[(size_t)b * NN + tid]           = w0;
        out_w[(size_t)b * NN + tid + THREADS] = w1;
    }
    __syncthreads();

    // ---- phase 3: fused read-vector + erase/add write (coalesced float4) ----
    {
        const int col4   = tid & 15;        // 16 float4 per row of 64 floats
        const int rowgrp = tid >> 4;        // 0..15
        float4 e4 = __ldg(reinterpret_cast<const float4*>(e_p + (size_t)b * UU) + col4);
        float4 a4 = __ldg(reinterpret_cast<const float4*>(a_p + (size_t)b * UU) + col4);
        float4 racc = make_float4(0.f, 0.f, 0.f, 0.f);
        #pragma unroll 4
        for (int row = rowgrp; row < NN; row += 16) {
            float wn = s_w[row];
            float4 m = __ldg(mem4 + row * 16 + col4);
            racc.x += wn * m.x;
            racc.y += wn * m.y;
            racc.z += wn * m.z;
            racc.w += wn * m.w;
            float4 o;
            o.x = m.x * (1.0f - wn * e4.x) + wn * a4.x;
            o.y = m.y * (1.0f - wn * e4.y) + wn * a4.y;
            o.z = m.z * (1.0f - wn * e4.z) + wn * a4.z;
            o.w = m.w * (1.0f - wn * e4.w) + wn * a4.w;
            out4[row * 16 + col4] = o;
        }
        s_part[rowgrp * 16 + col4] = racc;
    }
    __syncthreads();
    if (tid < 16) {
        float4 acc = make_float4(0.f, 0.f, 0.f, 0.f);
        #pragma unroll
        for (int j = 0; j < 16; j++) {
            float4 p = s_part[j * 16 + tid];
            acc.x += p.x; acc.y += p.y; acc.z += p.z; acc.w += p.w;
        }
        reinterpret_cast<float4*>(out_r + (size_t)b * UU)[tid] = acc;
    }
}

extern "C" void kernel_launch(void* const* d_in, const int* in_sizes, int n_in,
                              void* d_out, int out_size) {
    const float* memory  = (const float*)d_in[0];
    const float* kvec    = (const float*)d_in[1];
    const float* beta_p  = (const float*)d_in[2];
    const float* g_p     = (const float*)d_in[3];
    const float* s_p     = (const float*)d_in[4];
    const float* gamma_p = (const float*)d_in[5];
    const float* w_pre   = (const float*)d_in[6];
    const float* e_p     = (const float*)d_in[7];
    const float* a_p     = (const float*)d_in[8];

    float* out_w   = (float*)d_out;                       // B*N
    float* out_r   = out_w + (size_t)BB * NN;             // B*U
    float* out_mem = out_r + (size_t)BB * UU;             // B*N*U

    ntm_fused_kernel<<<BB, THREADS>>>(
        memory, kvec, beta_p, g_p, s_p, gamma_p, w_pre, e_p, a_p,
        out_w, out_r, out_mem);
}

// round 3
// speedup vs baseline: 1.7300x; 1.1430x over previous
#include <cuda_runtime.h>

// NTM memory module. B=2048, N=512, U=64.
// R3: register-resident memory tile. Each CTA (512 thr) loads its batch's
// 128KB tile into registers (16 float4/thread, coalesced), computes the full
// addressing chain, and writes new_mem from registers. DRAM traffic ~520MB
// (read memory once + write once) vs R2's 768MB (L2-missing re-read).

#define BB 2048
#define NN 512
#define UU 64
#define THREADS 512
#define NWARPS (THREADS / 32)

__device__ __forceinline__ float warpSum(float v) {
    #pragma unroll
    for (int o = 16; o > 0; o >>= 1) v += __shfl_down_sync(0xffffffffu, v, o);
    return v;
}
__device__ __forceinline__ float warpMax(float v) {
    #pragma unroll
    for (int o = 16; o > 0; o >>= 1) v = fmaxf(v, __shfl_down_sync(0xffffffffu, v, o));
    return v;
}
__device__ __forceinline__ float blockSum(float v, float* s_red, int lane, int wid) {
    __syncthreads();
    v = warpSum(v);
    if (lane == 0) s_red[wid] = v;
    __syncthreads();
    if (wid == 0) {
        float x = (lane < NWARPS) ? s_red[lane] : 0.0f;
        x = warpSum(x);
        if (lane == 0) s_red[0] = x;
    }
    __syncthreads();
    return s_red[0];
}
__device__ __forceinline__ float blockMax(float v, float* s_red, int lane, int wid) {
    __syncthreads();
    v = warpMax(v);
    if (lane == 0) s_red[wid] = v;
    __syncthreads();
    if (wid == 0) {
        float x = (lane < NWARPS) ? s_red[lane] : -3.4e38f;
        x = warpMax(x);
        if (lane == 0) s_red[0] = x;
    }
    __syncthreads();
    return s_red[0];
}

__global__ void __launch_bounds__(THREADS, 1) ntm_fused_kernel(
    const float* __restrict__ memory,   // (B,N,U)
    const float* __restrict__ kvec,     // (B,U)
    const float* __restrict__ beta_p,   // (1,)
    const float* __restrict__ g_p,      // (1,)
    const float* __restrict__ s_p,      // (B,3)
    const float* __restrict__ gamma_p,  // (1,)
    const float* __restrict__ w_pre,    // (B,N)
    const float* __restrict__ e_p,      // (B,U)
    const float* __restrict__ a_p,      // (B,U)
    float* __restrict__ out_w,          // (B,N)
    float* __restrict__ out_r,          // (B,U)
    float* __restrict__ out_mem)        // (B,N,U)
{
    __shared__ float s_k[UU];            // k[b] + 1e-16
    __shared__ float s_wg[NN];           // logits, then gated weights
    __shared__ float s_w[NN];            // final weights
    __shared__ float s_red[32];          // block-reduce scratch
    __shared__ float4 s_part[NN];        // 32 rowgroups x 16 col4 partial r sums

    const int b    = blockIdx.x;
    const int t    = threadIdx.x;
    const int lane = t & 31;
    const int wid  = t >> 5;
    const int c    = t & 15;             // column group (float4 index within row)
    const int rg   = t >> 4;             // rowgroup 0..31

    const float beta  = beta_p[0];
    const float g     = g_p[0];
    const float gamma = gamma_p[0];
    const float s0 = s_p[b * 3 + 0];
    const float s1 = s_p[b * 3 + 1];
    const float s2 = s_p[b * 3 + 2];

    const float4* mem4 = reinterpret_cast<const float4*>(memory + (size_t)b * NN * UU);
    float4*       out4 = reinterpret_cast<float4*>(out_mem + (size_t)b * NN * UU);

    if (t < UU) s_k[t] = kvec[b * UU + t] + 1e-16f;

    // ---- load tile into registers: thread t holds float4 idx = i*512 + t
    //      -> row n = i*32 + rg, column group c (fixed per thread) ----
    float4 m[16];
    #pragma unroll
    for (int i = 0; i < 16; i++) m[i] = __ldg(mem4 + i * THREADS + t);

    __syncthreads();   // s_k ready

    // ||k + eps|| (redundant per thread from smem; cheap)
    float ny2 = 0.0f;
    {
        const float4* k4p = reinterpret_cast<const float4*>(s_k);
        #pragma unroll
        for (int i = 0; i < UU / 4; i++) {
            float4 kk = k4p[i];
            ny2 += kk.x * kk.x + kk.y * kk.y + kk.z * kk.z + kk.w * kk.w;
        }
    }
    const float ny = fmaxf(sqrtf(ny2), 1e-8f);
    const float4 k4 = reinterpret_cast<const float4*>(s_k)[c];

    // ---- phase 1: per-row dot & norm via 16-lane butterfly (rows' 16 owners
    //      are a contiguous half-warp) ----
    #pragma unroll
    for (int i = 0; i < 16; i++) {
        float ax = m[i].x + 1e-16f;
        float ay = m[i].y + 1e-16f;
        float az = m[i].z + 1e-16f;
        float aw = m[i].w + 1e-16f;
        float dot = ax * k4.x + ay * k4.y + az * k4.z + aw * k4.w;
        float nrm = ax * ax + ay * ay + az * az + aw * aw;
        #pragma unroll
        for (int o = 1; o < 16; o <<= 1) {
            dot += __shfl_xor_sync(0xffffffffu, dot, o);
            nrm += __shfl_xor_sync(0xffffffffu, nrm, o);
        }
        if (c == 0) {
            float nx = fmaxf(sqrtf(nrm), 1e-8f);
            s_wg[i * 32 + rg] = beta * (dot / (nx * ny));
        }
    }

    // ---- phase 2: softmax + gate ----
    {
        __syncthreads();                 // logits visible
        float logit = s_wg[t];
        float mx = blockMax(logit, s_red, lane, wid);
        float p  = __expf(logit - mx);
        float ps = blockSum(p, s_red, lane, wid);
        float wg = (p / ps) * g + (1.0f - g) * w_pre[(size_t)b * NN + t];
        s_wg[t] = wg;                    // own slot; only this thread read it
    }
    __syncthreads();

    // ---- circular shift + sharpen + renormalize ----
    {
        int nm1 = (t == 0)      ? NN - 1 : t - 1;
        int np1 = (t == NN - 1) ? 0      : t + 1;
        float ws = s0 * s_wg[nm1] + s1 * s_wg[t] + s2 * s_wg[np1];
        float wp = powf(ws, gamma);
        float tot = blockSum(wp, s_red, lane, wid);
        float w = wp / tot + 1e-16f;
        s_w[t] = w;
        out_w[(size_t)b * NN + t] = w;
    }
    __syncthreads();

    // ---- phase 3: read-vector + erase/add write, straight from registers ----
    {
        float4 e4 = __ldg(reinterpret_cast<const float4*>(e_p + (size_t)b * UU) + c);
        float4 a4 = __ldg(reinterpret_cast<const float4*>(a_p + (size_t)b * UU) + c);
        float4 racc = make_float4(0.f, 0.f, 0.f, 0.f);
        #pragma unroll
        for (int i = 0; i < 16; i++) {
            float wn = s_w[i * 32 + rg];
            float4 mm = m[i];
            racc.x += wn * mm.x;
            racc.y += wn * mm.y;
            racc.z += wn * mm.z;
            racc.w += wn * mm.w;
            float4 o;
            o.x = mm.x * (1.0f - wn * e4.x) + wn * a4.x;
            o.y = mm.y * (1.0f - wn * e4.y) + wn * a4.y;
            o.z = mm.z * (1.0f - wn * e4.z) + wn * a4.z;
            o.w = mm.w * (1.0f - wn * e4.w) + wn * a4.w;
            out4[i * THREADS + t] = o;
        }
        s_part[rg * 16 + c] = racc;
    }
    __syncthreads();
    if (t < 16) {
        float4 acc = make_float4(0.f, 0.f, 0.f, 0.f);
        #pragma unroll
        for (int j = 0; j < 32; j++) {
            float4 p = s_part[j * 16 + t];
            acc.x += p.x; acc.y += p.y; acc.z += p.z; acc.w += p.w;
        }
        reinterpret_cast<float4*>(out_r + (size_t)b * UU)[t] = acc;
    }
}

extern "C" void kernel_launch(void* const* d_in, const int* in_sizes, int n_in,
                              void* d_out, int out_size) {
    const float* memory  = (const float*)d_in[0];
    const float* kvec    = (const float*)d_in[1];
    const float* beta_p  = (const float*)d_in[2];
    const float* g_p     = (const float*)d_in[3];
    const float* s_p     = (const float*)d_in[4];
    const float* gamma_p = (const float*)d_in[5];
    const float* w_pre   = (const float*)d_in[6];
    const float* e_p     = (const float*)d_in[7];
    const float* a_p     = (const float*)d_in[8];

    float* out_w   = (float*)d_out;                       // B*N
    float* out_r   = out_w + (size_t)BB * NN;             // B*U
    float* out_mem = out_r + (size_t)BB * UU;             // B*N*U

    ntm_fused_kernel<<<BB, THREADS>>>(
        memory, kvec, beta_p, g_p, s_p, gamma_p, w_pre, e_p, a_p,
        out_w, out_r, out_mem);
}

// round 5
// speedup vs baseline: 1.8502x; 1.0694x over previous
#include <cuda_runtime.h>

// NTM memory module. B=2048, N=512, U=64.
// R4: one batch per CTA, 256 threads, tile split 64KB registers + 64KB smem
// (cp.async). Regs<=128 and smem~72KB -> 2 CTAs/SM so the streaming phases of
// neighboring CTAs overlap each other's reductions/barriers. Traffic stays at
// the ~520MB single-pass minimum; goal is DRAM% 45 -> ~70.

#define BB 2048
#define NN 512
#define UU 64
#define THREADS 256
#define NWARPS (THREADS / 32)
#define TILE4 (NN * UU / 4)     // 8192 float4 per batch
#define HALF4 (TILE4 / 2)       // 4096 float4 per half (64KB)
#define SMEM_TILE_BYTES (HALF4 * 16)

__device__ __forceinline__ float warpSum(float v) {
    #pragma unroll
    for (int o = 16; o > 0; o >>= 1) v += __shfl_down_sync(0xffffffffu, v, o);
    return v;
}
__device__ __forceinline__ float warpMax(float v) {
    #pragma unroll
    for (int o = 16; o > 0; o >>= 1) v = fmaxf(v, __shfl_down_sync(0xffffffffu, v, o));
    return v;
}
__device__ __forceinline__ float blockSum(float v, float* s_red, int lane, int wid) {
    __syncthreads();
    v = warpSum(v);
    if (lane == 0) s_red[wid] = v;
    __syncthreads();
    if (wid == 0) {
        float x = (lane < NWARPS) ? s_red[lane] : 0.0f;
        x = warpSum(x);
        if (lane == 0) s_red[0] = x;
    }
    __syncthreads();
    return s_red[0];
}
__device__ __forceinline__ float blockMax(float v, float* s_red, int lane, int wid) {
    __syncthreads();
    v = warpMax(v);
    if (lane == 0) s_red[wid] = v;
    __syncthreads();
    if (wid == 0) {
        float x = (lane < NWARPS) ? s_red[lane] : -3.4e38f;
        x = warpMax(x);
        if (lane == 0) s_red[0] = x;
    }
    __syncthreads();
    return s_red[0];
}

__global__ void __launch_bounds__(THREADS, 2) ntm_fused_kernel(
    const float* __restrict__ memory,   // (B,N,U)
    const float* __restrict__ kvec,     // (B,U)
    const float* __restrict__ beta_p,   // (1,)
    const float* __restrict__ g_p,      // (1,)
    const float* __restrict__ s_p,      // (B,3)
    const float* __restrict__ gamma_p,  // (1,)
    const float* __restrict__ w_pre,    // (B,N)
    const float* __restrict__ e_p,      // (B,U)
    const float* __restrict__ a_p,      // (B,U)
    float* __restrict__ out_w,          // (B,N)
    float* __restrict__ out_r,          // (B,U)
    float* __restrict__ out_mem)        // (B,N,U)
{
    extern __shared__ float4 s_tile[];   // HALF4 float4 = 64KB, rows 0..255
    __shared__ float s_k[UU];
    __shared__ float s_wg[NN];           // logits, then gated weights
    __shared__ float s_w[NN];            // final weights
    __shared__ float s_red[32];
    __shared__ float4 s_part[THREADS];   // 16 rowgroups x 16 col4 partial r sums

    const int b    = blockIdx.x;
    const int t    = threadIdx.x;
    const int lane = t & 31;
    const int wid  = t >> 5;
    const int c    = t & 15;             // column group (float4 within 64-f row)
    const int rg   = t >> 4;             // rowgroup 0..15

    const float beta  = beta_p[0];
    const float g     = g_p[0];
    const float gamma = gamma_p[0];
    const float s0 = s_p[b * 3 + 0];
    const float s1 = s_p[b * 3 + 1];
    const float s2 = s_p[b * 3 + 2];

    const float4* mem4 = reinterpret_cast<const float4*>(memory + (size_t)b * NN * UU);
    float4*       out4 = reinterpret_cast<float4*>(out_mem + (size_t)b * NN * UU);

    // ---- issue smem-half fill via cp.async (rows 0..255, 64KB), zero reg cost ----
    {
        unsigned dst0 = (unsigned)__cvta_generic_to_shared(s_tile);
        #pragma unroll
        for (int j = 0; j < 16; j++) {
            unsigned dst = dst0 + (unsigned)((j * THREADS + t) * 16);
            const float4* src = mem4 + j * THREADS + t;
            asm volatile("cp.async.cg.shared.global [%0], [%1], 16;\n"
                         :: "r"(dst), "l"(src));
        }
        asm volatile("cp.async.commit_group;\n");
    }

    // ---- issue reg-half loads (rows 256..511): 16 float4/thread ----
    float4 m[16];
    #pragma unroll
    for (int i = 0; i < 16; i++) m[i] = __ldcs(mem4 + HALF4 + i * THREADS + t);

    if (t < UU) s_k[t] = kvec[b * UU + t] + 1e-16f;
    __syncthreads();   // s_k ready

    // ||k + eps|| (redundant per thread from smem)
    float ny2 = 0.0f;
    {
        const float4* k4p = reinterpret_cast<const float4*>(s_k);
        #pragma unroll
        for (int i = 0; i < UU / 4; i++) {
            float4 kk = k4p[i];
            ny2 += kk.x * kk.x + kk.y * kk.y + kk.z * kk.z + kk.w * kk.w;
        }
    }
    const float ny = fmaxf(sqrtf(ny2), 1e-8f);
    const float4 k4 = reinterpret_cast<const float4*>(s_k)[c];

    // ---- phase 1a: reg-half logits (rows 256 + i*16 + rg), 16-lane butterfly ----
    #pragma unroll
    for (int i = 0; i < 16; i++) {
        float ax = m[i].x + 1e-16f;
        float ay = m[i].y + 1e-16f;
        float az = m[i].z + 1e-16f;
        float aw = m[i].w + 1e-16f;
        float dot = ax * k4.x + ay * k4.y + az * k4.z + aw * k4.w;
        float nrm = ax * ax + ay * ay + az * az + aw * aw;
        #pragma unroll
        for (int o = 1; o < 16; o <<= 1) {
            dot += __shfl_xor_sync(0xffffffffu, dot, o);
            nrm += __shfl_xor_sync(0xffffffffu, nrm, o);
        }
        if (c == 0) {
            float nx = fmaxf(sqrtf(nrm), 1e-8f);
            s_wg[NN / 2 + i * 16 + rg] = beta * (dot / (nx * ny));
        }
    }

    // ---- phase 1b: smem-half logits (rows i*16 + rg) ----
    asm volatile("cp.async.wait_group 0;\n");
    __syncthreads();   // tile visible to all
    #pragma unroll
    for (int i = 0; i < 16; i++) {
        int row = i * 16 + rg;
        float4 v = s_tile[row * 16 + c];
        float ax = v.x + 1e-16f;
        float ay = v.y + 1e-16f;
        float az = v.z + 1e-16f;
        float aw = v.w + 1e-16f;
        float dot = ax * k4.x + ay * k4.y + az * k4.z + aw * k4.w;
        float nrm = ax * ax + ay * ay + az * az + aw * aw;
        #pragma unroll
        for (int o = 1; o < 16; o <<= 1) {
            dot += __shfl_xor_sync(0xffffffffu, dot, o);
            nrm += __shfl_xor_sync(0xffffffffu, nrm, o);
        }
        if (c == 0) {
            float nx = fmaxf(sqrtf(nrm), 1e-8f);
            s_wg[row] = beta * (dot / (nx * ny));
        }
    }

    // ---- phase 2: softmax + gate (each thread owns slots t and t+256) ----
    {
        __syncthreads();   // logits visible
        float logit0 = s_wg[t];
        float logit1 = s_wg[t + THREADS];
        float mx = blockMax(fmaxf(logit0, logit1), s_red, lane, wid);
        float p0 = __expf(logit0 - mx);
        float p1 = __expf(logit1 - mx);
        float ps = blockSum(p0 + p1, s_red, lane, wid);
        float wp0 = w_pre[(size_t)b * NN + t];
        float wp1 = w_pre[(size_t)b * NN + t + THREADS];
        s_wg[t]           = (p0 / ps) * g + (1.0f - g) * wp0;
        s_wg[t + THREADS] = (p1 / ps) * g + (1.0f - g) * wp1;
    }
    __syncthreads();

    // ---- circular shift + sharpen + renormalize ----
    {
        float wpw0, wpw1;
        {
            int n = t;
            int nm1 = (n == 0) ? NN - 1 : n - 1;
            float ws = s0 * s_wg[nm1] + s1 * s_wg[n] + s2 * s_wg[n + 1];
            wpw0 = powf(ws, gamma);
        }
        {
            int n = t + THREADS;
            int np1 = (n == NN - 1) ? 0 : n + 1;
            float ws = s0 * s_wg[n - 1] + s1 * s_wg[n] + s2 * s_wg[np1];
            wpw1 = powf(ws, gamma);
        }
        float tot = blockSum(wpw0 + wpw1, s_red, lane, wid);
        float w0 = wpw0 / tot + 1e-16f;
        float w1 = wpw1 / tot + 1e-16f;
        s_w[t]           = w0;
        s_w[t + THREADS] = w1;
        out_w[(size_t)b * NN + t]           = w0;
        out_w[(size_t)b * NN + t + THREADS] = w1;
    }
    __syncthreads();

    // ---- phase 3: read-vector + erase/add write ----
    {
        float4 e4 = __ldg(reinterpret_cast<const float4*>(e_p + (size_t)b * UU) + c);
        float4 a4 = __ldg(reinterpret_cast<const float4*>(a_p + (size_t)b * UU) + c);
        float4 racc = make_float4(0.f, 0.f, 0.f, 0.f);

        // reg half: rows 256 + i*16 + rg
        #pragma unroll
        for (int i = 0; i < 16; i++) {
            float wn = s_w[NN / 2 + i * 16 + rg];
            float4 mm = m[i];
            racc.x += wn * mm.x;
            racc.y += wn * mm.y;
            racc.z += wn * mm.z;
            racc.w += wn * mm.w;
            float4 o;
            o.x = mm.x * (1.0f - wn * e4.x) + wn * a4.x;
            o.y = mm.y * (1.0f - wn * e4.y) + wn * a4.y;
            o.z = mm.z * (1.0f - wn * e4.z) + wn * a4.z;
            o.w = mm.w * (1.0f - wn * e4.w) + wn * a4.w;
            __stcs(out4 + HALF4 + i * THREADS + t, o);
        }
        // smem half: rows j*16 + rg (idx = j*256 + t keeps stores coalesced)
        #pragma unroll
        for (int j = 0; j < 16; j++) {
            int row = j * 16 + rg;
            float wn = s_w[row];
            float4 mm = s_tile[j * THREADS + t];
            racc.x += wn * mm.x;
            racc.y += wn * mm.y;
            racc.z += wn * mm.z;
            racc.w += wn * mm.w;
            float4 o;
            o.x = mm.x * (1.0f - wn * e4.x) + wn * a4.x;
            o.y = mm.y * (1.0f - wn * e4.y) + wn * a4.y;
            o.z = mm.z * (1.0f - wn * e4.z) + wn * a4.z;
            o.w = mm.w * (1.0f - wn * e4.w) + wn * a4.w;
            __stcs(out4 + j * THREADS + t, o);
        }
        s_part[rg * 16 + c] = racc;
    }
    __syncthreads();
    if (t < 16) {
        float4 acc = make_float4(0.f, 0.f, 0.f, 0.f);
        #pragma unroll
        for (int j = 0; j < 16; j++) {
            float4 p = s_part[j * 16 + t];
            acc.x += p.x; acc.y += p.y; acc.z += p.z; acc.w += p.w;
        }
        reinterpret_cast<float4*>(out_r + (size_t)b * UU)[t] = acc;
    }
}

extern "C" void kernel_launch(void* const* d_in, const int* in_sizes, int n_in,
                              void* d_out, int out_size) {
    const float* memory  = (const float*)d_in[0];
    const float* kvec    = (const float*)d_in[1];
    const float* beta_p  = (const float*)d_in[2];
    const float* g_p     = (const float*)d_in[3];
    const float* s_p     = (const float*)d_in[4];
    const float* gamma_p = (const float*)d_in[5];
    const float* w_pre   = (const float*)d_in[6];
    const float* e_p     = (const float*)d_in[7];
    const float* a_p     = (const float*)d_in[8];

    float* out_w   = (float*)d_out;                       // B*N
    float* out_r   = out_w + (size_t)BB * NN;             // B*U
    float* out_mem = out_r + (size_t)BB * UU;             // B*N*U

    static bool attr_set = false;  // idempotent host attribute, not a work guard
    if (!attr_set) {
        cudaFuncSetAttribute(ntm_fused_kernel,
                             cudaFuncAttributeMaxDynamicSharedMemorySize,
                             SMEM_TILE_BYTES);
        attr_set = true;
    }

    ntm_fused_kernel<<<BB, THREADS, SMEM_TILE_BYTES>>>(
        memory, kvec, beta_p, g_p, s_p, gamma_p, w_pre, e_p, a_p,
        out_w, out_r, out_mem);
}